// round 2
// baseline (speedup 1.0000x reference)
#include <cuda_runtime.h>

// Problem constants
#define B_    32
#define C_    256
#define HW_   1024
#define N_    32768          // B_*HW_
#define K_    1024
#define QSIZE 8388608        // B_*C_*HW_

__device__ float g_enorm[K_];
__device__ float g_anorm[N_];
__device__ float g_loss;

__global__ void zero_loss_kernel() { g_loss = 0.0f; }

// ||e_k||^2 per codebook row
__global__ void enorm_kernel(const float* __restrict__ cb) {
    int k = blockIdx.x * blockDim.x + threadIdx.x;
    if (k < K_) {
        const float4* row = reinterpret_cast<const float4*>(cb + (size_t)k * C_);
        float s = 0.f;
        #pragma unroll
        for (int i = 0; i < C_ / 4; ++i) {
            float4 v = row[i];
            s += v.x * v.x + v.y * v.y + v.z * v.z + v.w * v.w;
        }
        g_enorm[k] = s;
    }
}

// ||z_n||^2 per flat row (n = b*1024 + hw). Coalesced: adjacent threads = adjacent hw.
__global__ void anorm_kernel(const float* __restrict__ x) {
    int n  = blockIdx.x * blockDim.x + threadIdx.x;   // 0..32767
    int b  = n >> 10;
    int hw = n & 1023;
    const float* p = x + (size_t)b * (C_ * HW_) + hw;
    float s = 0.f;
    #pragma unroll 8
    for (int c = 0; c < C_; ++c) {
        float v = p[(size_t)c * HW_];
        s += v * v;
    }
    g_anorm[n] = s;
}

__global__ void finalize_kernel(float* __restrict__ out) {
    out[QSIZE] = 1.25f * g_loss * (1.0f / (float)QSIZE);
}

// Fused: dot GEMM (128 rows x 1024 codes, C=256) + reference-faithful quantized
// distance d = fl(fl(a_n + b_k) - 2*m_nk) + argmin (lowest-index ties) + gather + MSE.
__global__ __launch_bounds__(256, 2)
void vq_main_kernel(const float* __restrict__ x,
                    const float* __restrict__ cb,
                    float* __restrict__ out)
{
    __shared__ float As[32][128];   // As[cc][m] : x slice, C-major
    __shared__ float Bs[32][132];   // Bs[cc][k] : codebook tile, padded
    __shared__ int   srow[128];
    __shared__ float wsum[8];

    const int tid = threadIdx.x;
    const int tx  = tid & 15;       // code direction
    const int ty  = tid >> 4;       // row direction

    const int blk = blockIdx.x;     // 256 blocks, never crosses batch boundary
    const int b   = blk >> 3;
    const int hw0 = (blk & 7) << 7;
    const int m0  = blk << 7;       // global flat-row base

    const float* xblk = x + (size_t)b * (C_ * HW_) + hw0;

    float minv[8];
    int   mini[8];
    float arow[8];
    #pragma unroll
    for (int i = 0; i < 8; ++i) {
        minv[i] = 3.4e38f; mini[i] = 0;
        arow[i] = g_anorm[m0 + ty * 8 + i];
    }

    for (int kt = 0; kt < 8; ++kt) {
        const int k0 = kt << 7;

        unsigned long long acc[8][4];
        #pragma unroll
        for (int i = 0; i < 8; ++i)
            #pragma unroll
            for (int j = 0; j < 4; ++j) acc[i][j] = 0ull;   // packs (0.0f, 0.0f)

        for (int ct = 0; ct < 8; ++ct) {
            const int c0 = ct << 5;
            __syncthreads();

            // A tile: As[cc][m] = x[b, c0+cc, hw0+m]  (coalesced float4)
            #pragma unroll
            for (int it = 0; it < 4; ++it) {
                int f4 = it * 256 + tid;          // 0..1023 float4 units
                int cc = f4 >> 5;
                int w  = (f4 & 31) << 2;
                float4 v = *reinterpret_cast<const float4*>(xblk + (c0 + cc) * HW_ + w);
                *reinterpret_cast<float4*>(&As[cc][w]) = v;
            }
            // B tile: Bs[cc][kk] = cb[(k0+kk)*C + c0+cc]
            #pragma unroll
            for (int it = 0; it < 16; ++it) {
                int l  = it * 256 + tid;          // 0..4095
                int cc = l & 31;
                int kk = l >> 5;
                Bs[cc][kk] = cb[(size_t)(k0 + kk) * C_ + (c0 + cc)];
            }
            __syncthreads();

            #pragma unroll 4
            for (int cc = 0; cc < 32; ++cc) {
                float4 a0 = *reinterpret_cast<const float4*>(&As[cc][ty * 8]);
                float4 a1 = *reinterpret_cast<const float4*>(&As[cc][ty * 8 + 4]);
                ulonglong2 p0 = *reinterpret_cast<const ulonglong2*>(&Bs[cc][tx * 8]);
                ulonglong2 p1 = *reinterpret_cast<const ulonglong2*>(&Bs[cc][tx * 8 + 4]);
                unsigned long long bv0 = p0.x, bv1 = p0.y, bv2 = p1.x, bv3 = p1.y;
                float a[8] = {a0.x, a0.y, a0.z, a0.w, a1.x, a1.y, a1.z, a1.w};
                #pragma unroll
                for (int i = 0; i < 8; ++i) {
                    unsigned long long av;
                    asm("mov.b64 %0, {%1, %1};" : "=l"(av) : "r"(__float_as_uint(a[i])));
                    asm("fma.rn.f32x2 %0, %1, %2, %0;" : "+l"(acc[i][0]) : "l"(av), "l"(bv0));
                    asm("fma.rn.f32x2 %0, %1, %2, %0;" : "+l"(acc[i][1]) : "l"(av), "l"(bv1));
                    asm("fma.rn.f32x2 %0, %1, %2, %0;" : "+l"(acc[i][2]) : "l"(av), "l"(bv2));
                    asm("fma.rn.f32x2 %0, %1, %2, %0;" : "+l"(acc[i][3]) : "l"(av), "l"(bv3));
                }
            }
        }

        // Reference-faithful quantized distance: d = fl(fl(a + b_k) - 2*m).
        float en[8];
        #pragma unroll
        for (int j = 0; j < 8; ++j) en[j] = g_enorm[k0 + tx * 8 + j];
        #pragma unroll
        for (int i = 0; i < 8; ++i) {
            #pragma unroll
            for (int j = 0; j < 4; ++j) {
                float lo = __uint_as_float((unsigned int)(acc[i][j] & 0xffffffffull));
                float hi = __uint_as_float((unsigned int)(acc[i][j] >> 32));
                float A0 = arow[i] + en[2 * j];       // fl(a + b)  (grid ~ulp(256))
                float A1 = arow[i] + en[2 * j + 1];
                float s0 = A0 - 2.0f * lo;            // fl(A - 2m), single rounding
                float s1 = A1 - 2.0f * hi;
                int kb = k0 + tx * 8 + 2 * j;
                if (s0 < minv[i]) { minv[i] = s0; mini[i] = kb; }
                if (s1 < minv[i]) { minv[i] = s1; mini[i] = kb + 1; }
            }
        }
    }

    // Reduce across the 16 threads (tx) sharing each row; lowest index on ties.
    #pragma unroll
    for (int i = 0; i < 8; ++i) {
        float v  = minv[i];
        int  idx = mini[i];
        #pragma unroll
        for (int off = 8; off; off >>= 1) {
            float ov = __shfl_xor_sync(0xffffffffu, v, off);
            int   oi = __shfl_xor_sync(0xffffffffu, idx, off);
            if (ov < v || (ov == v && oi < idx)) { v = ov; idx = oi; }
        }
        if (tx == 0) {
            int m = ty * 8 + i;
            srow[m] = idx;
            out[QSIZE + 1 + m0 + m] = (float)idx;   // indices output (as f32)
        }
    }
    __syncthreads();

    // Cooperative gather + straight-through emulation (out = x + fl(q - x)) + MSE.
    float* qblk = out + (size_t)b * (C_ * HW_) + hw0;
    float lsum = 0.f;
    #pragma unroll 4
    for (int it = 0; it < 32; ++it) {
        int l  = it * 256 + tid;         // float4 units over [c][m/4]
        int m4 = (l & 31) << 2;
        int c  = l >> 5;
        float4 xv = *reinterpret_cast<const float4*>(xblk + c * HW_ + m4);
        float q0 = __ldg(cb + (size_t)srow[m4 + 0] * C_ + c);
        float q1 = __ldg(cb + (size_t)srow[m4 + 1] * C_ + c);
        float q2 = __ldg(cb + (size_t)srow[m4 + 2] * C_ + c);
        float q3 = __ldg(cb + (size_t)srow[m4 + 3] * C_ + c);
        float d0 = q0 - xv.x, d1 = q1 - xv.y, d2 = q2 - xv.z, d3 = q3 - xv.w;
        float4 o;
        o.x = xv.x + d0; o.y = xv.y + d1; o.z = xv.z + d2; o.w = xv.w + d3;
        *reinterpret_cast<float4*>(qblk + c * HW_ + m4) = o;
        lsum += d0 * d0 + d1 * d1 + d2 * d2 + d3 * d3;
    }

    #pragma unroll
    for (int off = 16; off; off >>= 1)
        lsum += __shfl_xor_sync(0xffffffffu, lsum, off);
    if ((tid & 31) == 0) wsum[tid >> 5] = lsum;
    __syncthreads();
    if (tid == 0) {
        float s = 0.f;
        #pragma unroll
        for (int w = 0; w < 8; ++w) s += wsum[w];
        atomicAdd(&g_loss, s);
    }
}

extern "C" void kernel_launch(void* const* d_in, const int* in_sizes, int n_in,
                              void* d_out, int out_size) {
    (void)in_sizes; (void)n_in; (void)out_size;
    const float* x  = (const float*)d_in[0];
    const float* cb = (const float*)d_in[1];
    float* out = (float*)d_out;

    zero_loss_kernel<<<1, 1>>>();
    enorm_kernel<<<4, 256>>>(cb);
    anorm_kernel<<<128, 256>>>(x);
    vq_main_kernel<<<256, 256>>>(x, cb, out);
    finalize_kernel<<<1, 1>>>(out);
}

// round 3
// speedup vs baseline: 1.1859x; 1.1859x over previous
#include <cuda_runtime.h>

// Problem constants
#define B_    32
#define C_    256
#define HW_   1024
#define N_    32768          // B_*HW_
#define K_    1024
#define QSIZE 8388608        // B_*C_*HW_

__device__ float g_enorm[K_];
__device__ float g_anorm[N_];
__device__ float g_loss;

__global__ void zero_loss_kernel() { g_loss = 0.0f; }

// ||e_k||^2 per codebook row
__global__ void enorm_kernel(const float* __restrict__ cb) {
    int k = blockIdx.x * blockDim.x + threadIdx.x;
    if (k < K_) {
        const float4* row = reinterpret_cast<const float4*>(cb + (size_t)k * C_);
        float s = 0.f;
        #pragma unroll
        for (int i = 0; i < C_ / 4; ++i) {
            float4 v = row[i];
            s += v.x * v.x + v.y * v.y + v.z * v.z + v.w * v.w;
        }
        g_enorm[k] = s;
    }
}

// ||z_n||^2 per flat row (n = b*1024 + hw).
__global__ void anorm_kernel(const float* __restrict__ x) {
    int n  = blockIdx.x * blockDim.x + threadIdx.x;
    int b  = n >> 10;
    int hw = n & 1023;
    const float* p = x + (size_t)b * (C_ * HW_) + hw;
    float s = 0.f;
    #pragma unroll 8
    for (int c = 0; c < C_; ++c) {
        float v = p[(size_t)c * HW_];
        s += v * v;
    }
    g_anorm[n] = s;
}

__global__ void finalize_kernel(float* __restrict__ out) {
    out[QSIZE] = 1.25f * g_loss * (1.0f / (float)QSIZE);
}

// ---------------------------------------------------------------------------
// Main fused kernel. 256 threads (16 tx x 16 ty), 8x8 micro-tile per thread.
// Double-buffered 16-cc deep tiles; As via cp.async, Bs via reg prefetch.
// Conflict-free LDS: thread tx owns k in {tx*4..+3} u {64+tx*4..+3}.
// ---------------------------------------------------------------------------

#define CCT 16               // cc-tile depth
#define BS_PITCH 132

__device__ __forceinline__ void cp_async16(void* smem_dst, const void* gsrc) {
    unsigned d = (unsigned)__cvta_generic_to_shared(smem_dst);
    asm volatile("cp.async.cg.shared.global [%0], [%1], 16;\n" :: "r"(d), "l"(gsrc));
}

__global__ __launch_bounds__(256, 2)
void vq_main_kernel(const float* __restrict__ x,
                    const float* __restrict__ cb,
                    float* __restrict__ out)
{
    __shared__ __align__(16) float As[2][CCT][128];
    __shared__ __align__(16) float Bs[2][CCT][BS_PITCH];
    __shared__ int   srow[128];
    __shared__ float wsum[8];

    const int tid = threadIdx.x;
    const int tx  = tid & 15;       // code direction
    const int ty  = tid >> 4;       // row direction

    const int blk = blockIdx.x;
    const int b   = blk >> 3;
    const int hw0 = (blk & 7) << 7;
    const int m0  = blk << 7;

    const float* xblk = x + (size_t)b * (C_ * HW_) + hw0;

    // ---- tile fill helpers (inline) -------------------------------------
    // As fill: 2 x 16B cp.async per thread. unit u: cc = u>>5, m4 = (u&31)*4
    // Bs fill: 2 x float4 LDG per thread.   unit u: kk = u>>2, cq = u&3

    const int as_cc0 = tid >> 5;            // u = tid        -> cc, m4
    const int as_m0  = (tid & 31) << 2;
    const int as_cc1 = (256 + tid) >> 5;    // u = 256 + tid
    const int as_m1  = as_m0;               // (u&31) identical

    const int bk  = tid >> 2;               // kk for u = tid (0..63)
    const int bcq = (tid & 3) << 2;         // cc base = cq*4

    // ---- prologue: fill tile 0 into buf 0 --------------------------------
    {
        const int k0 = 0, c0 = 0;
        cp_async16(&As[0][as_cc0][as_m0], xblk + (c0 + as_cc0) * HW_ + as_m0);
        cp_async16(&As[0][as_cc1][as_m1], xblk + (c0 + as_cc1) * HW_ + as_m1);
        float4 f0 = *reinterpret_cast<const float4*>(cb + (size_t)(k0 + bk) * C_ + c0 + bcq);
        float4 f1 = *reinterpret_cast<const float4*>(cb + (size_t)(k0 + bk + 64) * C_ + c0 + bcq);
        Bs[0][bcq + 0][bk] = f0.x;  Bs[0][bcq + 1][bk] = f0.y;
        Bs[0][bcq + 2][bk] = f0.z;  Bs[0][bcq + 3][bk] = f0.w;
        Bs[0][bcq + 0][bk + 64] = f1.x;  Bs[0][bcq + 1][bk + 64] = f1.y;
        Bs[0][bcq + 2][bk + 64] = f1.z;  Bs[0][bcq + 3][bk + 64] = f1.w;
        asm volatile("cp.async.commit_group;");
        asm volatile("cp.async.wait_group 0;");
    }
    __syncthreads();

    float minv[8];
    int   mini[8];
    float arow[8];
    #pragma unroll
    for (int i = 0; i < 8; ++i) {
        minv[i] = 3.4e38f; mini[i] = 0;
        arow[i] = g_anorm[m0 + ty * 8 + i];
    }

    for (int kt = 0; kt < 8; ++kt) {
        const int k0 = kt << 7;

        unsigned long long acc[8][4];
        #pragma unroll
        for (int i = 0; i < 8; ++i)
            #pragma unroll
            for (int j = 0; j < 4; ++j) acc[i][j] = 0ull;

        for (int ct = 0; ct < 16; ++ct) {
            const int t   = (kt << 4) | ct;
            const int buf = t & 1;
            const bool pf = (t < 127);
            const int tn  = t + 1;
            const int k0n = (tn >> 4) << 7;
            const int c0n = (tn & 15) << 4;
            const int nb  = tn & 1;

            float4 f0, f1;
            if (pf) {
                // start prefetch of next tile
                cp_async16(&As[nb][as_cc0][as_m0], xblk + (c0n + as_cc0) * HW_ + as_m0);
                cp_async16(&As[nb][as_cc1][as_m1], xblk + (c0n + as_cc1) * HW_ + as_m1);
                asm volatile("cp.async.commit_group;");
                f0 = *reinterpret_cast<const float4*>(cb + (size_t)(k0n + bk) * C_ + c0n + bcq);
                f1 = *reinterpret_cast<const float4*>(cb + (size_t)(k0n + bk + 64) * C_ + c0n + bcq);
            }

            // ---- compute 16 cc on current buffer -------------------------
            #pragma unroll 8
            for (int cc = 0; cc < CCT; ++cc) {
                float4 a0 = *reinterpret_cast<const float4*>(&As[buf][cc][ty * 8]);
                float4 a1 = *reinterpret_cast<const float4*>(&As[buf][cc][ty * 8 + 4]);
                ulonglong2 q0 = *reinterpret_cast<const ulonglong2*>(&Bs[buf][cc][tx * 4]);
                ulonglong2 q1 = *reinterpret_cast<const ulonglong2*>(&Bs[buf][cc][64 + tx * 4]);
                unsigned long long bv0 = q0.x, bv1 = q0.y, bv2 = q1.x, bv3 = q1.y;
                float a[8] = {a0.x, a0.y, a0.z, a0.w, a1.x, a1.y, a1.z, a1.w};
                #pragma unroll
                for (int i = 0; i < 8; ++i) {
                    unsigned long long av;
                    asm("mov.b64 %0, {%1, %1};" : "=l"(av) : "r"(__float_as_uint(a[i])));
                    asm("fma.rn.f32x2 %0, %1, %2, %0;" : "+l"(acc[i][0]) : "l"(av), "l"(bv0));
                    asm("fma.rn.f32x2 %0, %1, %2, %0;" : "+l"(acc[i][1]) : "l"(av), "l"(bv1));
                    asm("fma.rn.f32x2 %0, %1, %2, %0;" : "+l"(acc[i][2]) : "l"(av), "l"(bv2));
                    asm("fma.rn.f32x2 %0, %1, %2, %0;" : "+l"(acc[i][3]) : "l"(av), "l"(bv3));
                }
            }

            if (pf) {
                Bs[nb][bcq + 0][bk] = f0.x;  Bs[nb][bcq + 1][bk] = f0.y;
                Bs[nb][bcq + 2][bk] = f0.z;  Bs[nb][bcq + 3][bk] = f0.w;
                Bs[nb][bcq + 0][bk + 64] = f1.x;  Bs[nb][bcq + 1][bk + 64] = f1.y;
                Bs[nb][bcq + 2][bk + 64] = f1.z;  Bs[nb][bcq + 3][bk + 64] = f1.w;
            }
            asm volatile("cp.async.wait_group 0;");
            __syncthreads();
        }

        // Reference-faithful quantized distance: d = fl(fl(a + b_k) - 2*m).
        // Thread's k set: pair j -> k = k0 + (j>>1)*64 + tx*4 + (j&1)*2 (+lane)
        float en[8];
        #pragma unroll
        for (int jj = 0; jj < 8; ++jj)
            en[jj] = g_enorm[k0 + (jj >> 2) * 64 + tx * 4 + (jj & 3)];
        #pragma unroll
        for (int i = 0; i < 8; ++i) {
            #pragma unroll
            for (int j = 0; j < 4; ++j) {
                float lo = __uint_as_float((unsigned int)(acc[i][j] & 0xffffffffull));
                float hi = __uint_as_float((unsigned int)(acc[i][j] >> 32));
                int e0 = (j >> 1) * 4 + (j & 1) * 2;
                float A0 = arow[i] + en[e0];
                float A1 = arow[i] + en[e0 + 1];
                float s0 = A0 - 2.0f * lo;
                float s1 = A1 - 2.0f * hi;
                int kb = k0 + (j >> 1) * 64 + tx * 4 + (j & 1) * 2;
                if (s0 < minv[i]) { minv[i] = s0; mini[i] = kb; }
                if (s1 < minv[i]) { minv[i] = s1; mini[i] = kb + 1; }
            }
        }
    }

    // Reduce across the 16 tx threads per row; lowest index on ties.
    #pragma unroll
    for (int i = 0; i < 8; ++i) {
        float v  = minv[i];
        int  idx = mini[i];
        #pragma unroll
        for (int off = 8; off; off >>= 1) {
            float ov = __shfl_xor_sync(0xffffffffu, v, off);
            int   oi = __shfl_xor_sync(0xffffffffu, idx, off);
            if (ov < v || (ov == v && oi < idx)) { v = ov; idx = oi; }
        }
        if (tx == 0) {
            int m = ty * 8 + i;
            srow[m] = idx;
            out[QSIZE + 1 + m0 + m] = (float)idx;
        }
    }
    __syncthreads();

    // Gather + straight-through (out = x + fl(q - x)) + MSE accumulation.
    float* qblk = out + (size_t)b * (C_ * HW_) + hw0;
    float lsum = 0.f;
    #pragma unroll 4
    for (int it = 0; it < 32; ++it) {
        int l  = it * 256 + tid;
        int m4 = (l & 31) << 2;
        int c  = l >> 5;
        float4 xv = *reinterpret_cast<const float4*>(xblk + c * HW_ + m4);
        float q0 = __ldg(cb + (size_t)srow[m4 + 0] * C_ + c);
        float q1 = __ldg(cb + (size_t)srow[m4 + 1] * C_ + c);
        float q2 = __ldg(cb + (size_t)srow[m4 + 2] * C_ + c);
        float q3 = __ldg(cb + (size_t)srow[m4 + 3] * C_ + c);
        float d0 = q0 - xv.x, d1 = q1 - xv.y, d2 = q2 - xv.z, d3 = q3 - xv.w;
        float4 o;
        o.x = xv.x + d0; o.y = xv.y + d1; o.z = xv.z + d2; o.w = xv.w + d3;
        *reinterpret_cast<float4*>(qblk + c * HW_ + m4) = o;
        lsum += d0 * d0 + d1 * d1 + d2 * d2 + d3 * d3;
    }

    #pragma unroll
    for (int off = 16; off; off >>= 1)
        lsum += __shfl_xor_sync(0xffffffffu, lsum, off);
    if ((tid & 31) == 0) wsum[tid >> 5] = lsum;
    __syncthreads();
    if (tid == 0) {
        float s = 0.f;
        #pragma unroll
        for (int w = 0; w < 8; ++w) s += wsum[w];
        atomicAdd(&g_loss, s);
    }
}

extern "C" void kernel_launch(void* const* d_in, const int* in_sizes, int n_in,
                              void* d_out, int out_size) {
    (void)in_sizes; (void)n_in; (void)out_size;
    const float* x  = (const float*)d_in[0];
    const float* cb = (const float*)d_in[1];
    float* out = (float*)d_out;

    zero_loss_kernel<<<1, 1>>>();
    enorm_kernel<<<4, 256>>>(cb);
    anorm_kernel<<<128, 256>>>(x);
    vq_main_kernel<<<256, 256>>>(x, cb, out);
    finalize_kernel<<<1, 1>>>(out);
}

// round 8
// speedup vs baseline: 1.2294x; 1.0367x over previous
#include <cuda_runtime.h>
#include <cuda_bf16.h>
#include <cstdint>

// Problem constants
#define B_    32
#define C_    256
#define HW_   1024
#define N_    32768          // B_*HW_
#define K_    1024
#define QSIZE 8388608        // B_*C_*HW_
#define KEXT  768            // 3 bf16 planes concatenated along K

__device__ float g_enorm[K_];
__device__ float g_anorm[N_];
__device__ float g_loss;
__device__ int   g_idx[N_];
__device__ float g_dist[(size_t)N_ * K_];             // 128 MB approx distances
__device__ __nv_bfloat16 g_Aext[(size_t)N_ * KEXT];   // x rows, [n][768]
__device__ __nv_bfloat16 g_Bext[(size_t)K_ * KEXT];   // codebook, [k][768]

// ---------------------------------------------------------------------------
// PTX helpers (plain PTX only: valid on compute_103 base target)
// ---------------------------------------------------------------------------
__device__ __forceinline__ uint32_t smem_u32(const void* p) {
    uint32_t a;
    asm("{ .reg .u64 t; cvta.to.shared.u64 t, %1; cvt.u32.u64 %0, t; }" : "=r"(a) : "l"(p));
    return a;
}
__device__ __forceinline__ void cp16(uint32_t daddr, const void* g) {
    asm volatile("cp.async.cg.shared.global [%0], [%1], 16;" :: "r"(daddr), "l"(g));
}
#define CP_COMMIT()  asm volatile("cp.async.commit_group;")
#define CP_WAIT0()   asm volatile("cp.async.wait_group 0;")

__device__ __forceinline__ void ldsm4(uint32_t* r, uint32_t addr) {
    asm volatile("ldmatrix.sync.aligned.m8n8.x4.shared.b16 {%0,%1,%2,%3}, [%4];"
        : "=r"(r[0]), "=r"(r[1]), "=r"(r[2]), "=r"(r[3]) : "r"(addr));
}
__device__ __forceinline__ void mma16816(float* d, const uint32_t* a, const uint32_t* b) {
    asm volatile(
        "mma.sync.aligned.m16n8k16.row.col.f32.bf16.bf16.f32 "
        "{%0,%1,%2,%3},{%4,%5,%6,%7},{%8,%9},{%0,%1,%2,%3};"
        : "+f"(d[0]), "+f"(d[1]), "+f"(d[2]), "+f"(d[3])
        : "r"(a[0]), "r"(a[1]), "r"(a[2]), "r"(a[3]), "r"(b[0]), "r"(b[1]));
}

// ---------------------------------------------------------------------------
// Prep kernels (anorm/enorm byte-identical to the R2 kernel that passed)
// ---------------------------------------------------------------------------
__global__ void zero_loss_kernel() { g_loss = 0.0f; }

__global__ void enorm_kernel(const float* __restrict__ cb) {
    int k = blockIdx.x * blockDim.x + threadIdx.x;
    if (k < K_) {
        const float4* row = reinterpret_cast<const float4*>(cb + (size_t)k * C_);
        float s = 0.f;
        #pragma unroll
        for (int i = 0; i < C_ / 4; ++i) {
            float4 v = row[i];
            s += v.x * v.x + v.y * v.y + v.z * v.z + v.w * v.w;
        }
        g_enorm[k] = s;
    }
}

__global__ void anorm_kernel(const float* __restrict__ x) {
    int n  = blockIdx.x * blockDim.x + threadIdx.x;
    int b  = n >> 10;
    int hw = n & 1023;
    const float* p = x + (size_t)b * (C_ * HW_) + hw;
    float s = 0.f;
    #pragma unroll 8
    for (int c = 0; c < C_; ++c) {
        float v = p[(size_t)c * HW_];
        s += v * v;
    }
    g_anorm[n] = s;
}

__global__ void finalize_kernel(float* __restrict__ out) {
    out[QSIZE] = 1.25f * g_loss * (1.0f / (float)QSIZE);
}

// Split codebook rows into 3 bf16 planes at k-offsets 0 / 256 / 512.
__global__ void prep_cb_kernel(const float* __restrict__ cb) {
    int i = blockIdx.x * blockDim.x + threadIdx.x;   // 0 .. 262143
    int row = i >> 8, c = i & 255;
    float v = cb[i];
    __nv_bfloat16 h = __float2bfloat16_rn(v);
    float r = v - __bfloat162float(h);
    __nv_bfloat16 m = __float2bfloat16_rn(r);
    float r2 = r - __bfloat162float(m);
    __nv_bfloat16 l = __float2bfloat16_rn(r2);
    size_t o = (size_t)row * KEXT + c;
    g_Bext[o] = h; g_Bext[o + 256] = m; g_Bext[o + 512] = l;
}

// Transpose x [b][c][hw] -> A_ext[n][c-planes] and split into 3 bf16 planes.
__global__ void prep_x_kernel(const float* __restrict__ x) {
    __shared__ float tile[64][65];
    int bid = blockIdx.x;          // 2048 blocks
    int b   = bid >> 6;
    int rem = bid & 63;
    int c0  = (rem >> 4) << 6;     // 0,64,128,192
    int hw0 = (rem & 15) << 6;     // 0..960
    int tid = threadIdx.x;

    #pragma unroll
    for (int i = 0; i < 16; ++i) {
        int cc = i * 4 + (tid >> 6);
        int hw = tid & 63;
        tile[cc][hw] = x[((size_t)b * C_ + c0 + cc) * HW_ + hw0 + hw];
    }
    __syncthreads();
    #pragma unroll
    for (int i = 0; i < 16; ++i) {
        int hh = i * 4 + (tid >> 6);
        int ci = tid & 63;
        float v = tile[ci][hh];
        __nv_bfloat16 h = __float2bfloat16_rn(v);
        float r = v - __bfloat162float(h);
        __nv_bfloat16 m = __float2bfloat16_rn(r);
        float r2 = r - __bfloat162float(m);
        __nv_bfloat16 l = __float2bfloat16_rn(r2);
        size_t o = (size_t)(b * HW_ + hw0 + hh) * KEXT + c0 + ci;
        g_Aext[o] = h; g_Aext[o + 256] = m; g_Aext[o + 512] = l;
    }
}

// ---------------------------------------------------------------------------
// GEMM kernel. CTA: 128 M x 256 N, K = 768. 8 warps (2M x 4N), warp tile
// 64x64, m16n8k16 bf16 HMMA, double-buffered cp.async K-chunks (64).
// Epilogue writes quantized approx distances to g_dist.
// ---------------------------------------------------------------------------
#define APITCH 72
#define ABUF_B (128 * APITCH * 2)       // 18432
#define BBUF_B (256 * APITCH * 2)       // 36864
#define SM_GEMM (2 * ABUF_B + 2 * BBUF_B)  // 110592

__global__ __launch_bounds__(256, 1)
void vq_gemm_kernel()
{
    extern __shared__ __align__(16) char dsm[];
    const uint32_t smA = smem_u32(dsm);
    const uint32_t smB = smA + 2 * ABUF_B;

    const int tid  = threadIdx.x;
    const int lane = tid & 31;
    const int wid  = tid >> 5;
    const int wm   = wid >> 2;          // 0..1
    const int wn   = wid & 3;           // 0..3

    const int m0 = blockIdx.x << 7;     // 128 rows per CTA
    const int n0 = blockIdx.y << 8;     // 256 codes per CTA

    const __nv_bfloat16* Ag = g_Aext + (size_t)m0 * KEXT;
    const __nv_bfloat16* Bg = g_Bext + (size_t)n0 * KEXT;

    float acc[4][8][4];
    #pragma unroll
    for (int mf = 0; mf < 4; ++mf)
        #pragma unroll
        for (int nf = 0; nf < 8; ++nf)
            #pragma unroll
            for (int q = 0; q < 4; ++q) acc[mf][nf][q] = 0.f;

    const uint32_t aAddr0 = smA + (uint32_t)(((wm * 64 + (lane & 15)) * APITCH + ((lane >> 4) << 3)) * 2);
    const uint32_t bAddr0 = smB + (uint32_t)(((wn * 64 + (lane & 7) + ((lane >> 4) << 3)) * APITCH
                                              + (((lane >> 3) & 1) << 3)) * 2);

    // chunk loader: A = 128x64 (1024 pieces), B = 256x64 (2048 pieces);
    // piece p: row = p >> 3, kp = (p & 7) * 8 elements.
    {
        #pragma unroll
        for (int j = 0; j < 4; ++j) {
            int p = tid + j * 256, row = p >> 3, kp = (p & 7) << 3;
            cp16(smA + (uint32_t)((row * APITCH + kp) * 2), Ag + (size_t)row * KEXT + kp);
        }
        #pragma unroll
        for (int j = 0; j < 8; ++j) {
            int p = tid + j * 256, row = p >> 3, kp = (p & 7) << 3;
            cp16(smB + (uint32_t)((row * APITCH + kp) * 2), Bg + (size_t)row * KEXT + kp);
        }
        CP_COMMIT();
    }

    for (int it = 0; it < 12; ++it) {
        CP_WAIT0();
        __syncthreads();

        if (it + 1 < 12) {
            const int nb = (it + 1) & 1;
            const int k0 = (it + 1) << 6;
            const __nv_bfloat16* As = Ag + k0;
            const __nv_bfloat16* Bs = Bg + k0;
            #pragma unroll
            for (int j = 0; j < 4; ++j) {
                int p = tid + j * 256, row = p >> 3, kp = (p & 7) << 3;
                cp16(smA + (uint32_t)(nb * ABUF_B + (row * APITCH + kp) * 2),
                     As + (size_t)row * KEXT + kp);
            }
            #pragma unroll
            for (int j = 0; j < 8; ++j) {
                int p = tid + j * 256, row = p >> 3, kp = (p & 7) << 3;
                cp16(smB + (uint32_t)(nb * BBUF_B + (row * APITCH + kp) * 2),
                     Bs + (size_t)row * KEXT + kp);
            }
            CP_COMMIT();
        }

        const int buf = it & 1;
        const uint32_t aB = aAddr0 + (uint32_t)(buf * ABUF_B);
        const uint32_t bB = bAddr0 + (uint32_t)(buf * BBUF_B);

        #pragma unroll
        for (int ks = 0; ks < 4; ++ks) {
            uint32_t a[4][4], bfr[4][4];
            #pragma unroll
            for (int mf = 0; mf < 4; ++mf)
                ldsm4(a[mf], aB + (uint32_t)(mf * 16 * APITCH * 2 + ks * 32));
            #pragma unroll
            for (int nb2 = 0; nb2 < 4; ++nb2)
                ldsm4(bfr[nb2], bB + (uint32_t)(nb2 * 16 * APITCH * 2 + ks * 32));
            #pragma unroll
            for (int mf = 0; mf < 4; ++mf)
                #pragma unroll
                for (int nf = 0; nf < 8; ++nf)
                    mma16816(acc[mf][nf], a[mf], &bfr[nf >> 1][(nf & 1) << 1]);
        }
    }

    // Epilogue: quantized approx distance -> g_dist[row][col].
    // acc frag (mf,nf): d0=(r,c) d1=(r,c+1) d2=(r+8,c) d3=(r+8,c+1),
    // r = mf*16 + lane/4 (+8), c = nf*8 + 2*(lane&3).
    const int rbase = m0 + wm * 64 + (lane >> 2);
    const int cbase = n0 + wn * 64 + ((lane & 3) << 1);
    #pragma unroll
    for (int mf = 0; mf < 4; ++mf) {
        #pragma unroll
        for (int half = 0; half < 2; ++half) {
            int row = rbase + mf * 16 + half * 8;
            float a = g_anorm[row];
            float* drow = g_dist + (size_t)row * K_;
            #pragma unroll
            for (int nf = 0; nf < 8; ++nf) {
                int col = cbase + nf * 8;
                float s0 = (a + g_enorm[col])     - 2.0f * acc[mf][nf][half * 2 + 0];
                float s1 = (a + g_enorm[col + 1]) - 2.0f * acc[mf][nf][half * 2 + 1];
                *reinterpret_cast<float2*>(drow + col) = make_float2(s0, s1);
            }
        }
    }
}

// ---------------------------------------------------------------------------
// Recheck kernel: 1 warp per row. Approx min over 1024 dists, then exact
// fp32 requantized distance for candidates within DELTA of the min.
// DELTA = 2e-3 ~ 50x the measured HMMA distance-error sigma (3-4e-5).
// ---------------------------------------------------------------------------
#define DELTA 2e-3f

__global__ __launch_bounds__(256)
void recheck_kernel(const float* __restrict__ cb)
{
    __shared__ float xrow[8][256];
    const int lane = threadIdx.x & 31;
    const int wid  = threadIdx.x >> 5;
    const int row  = blockIdx.x * 8 + wid;

    // Reconstruct fp32 x row from the 3 bf16 planes (err <= 2^-25 rel).
    {
        const __nv_bfloat16* ar = g_Aext + (size_t)row * KEXT;
        uint4 hv = *reinterpret_cast<const uint4*>(ar + lane * 8);
        uint4 mv = *reinterpret_cast<const uint4*>(ar + 256 + lane * 8);
        uint4 lv = *reinterpret_cast<const uint4*>(ar + 512 + lane * 8);
        const __nv_bfloat16* hp = reinterpret_cast<const __nv_bfloat16*>(&hv);
        const __nv_bfloat16* mp = reinterpret_cast<const __nv_bfloat16*>(&mv);
        const __nv_bfloat16* lp = reinterpret_cast<const __nv_bfloat16*>(&lv);
        #pragma unroll
        for (int j = 0; j < 8; ++j)
            xrow[wid][lane * 8 + j] = __bfloat162float(hp[j])
                                    + __bfloat162float(mp[j])
                                    + __bfloat162float(lp[j]);
    }
    __syncwarp();

    // Pass 1: approx min (packed value|index -> lowest index on ties).
    const float* drow = g_dist + (size_t)row * K_;
    float dv[32];
    unsigned long long best = 0xFFFFFFFFFFFFFFFFull;
    #pragma unroll
    for (int i = 0; i < 8; ++i) {
        float4 v = *reinterpret_cast<const float4*>(drow + i * 128 + lane * 4);
        int kb = i * 128 + lane * 4;
        dv[i * 4 + 0] = v.x; dv[i * 4 + 1] = v.y;
        dv[i * 4 + 2] = v.z; dv[i * 4 + 3] = v.w;
        unsigned long long p;
        p = ((unsigned long long)__float_as_uint(v.x) << 32) | (unsigned)(kb + 0); if (p < best) best = p;
        p = ((unsigned long long)__float_as_uint(v.y) << 32) | (unsigned)(kb + 1); if (p < best) best = p;
        p = ((unsigned long long)__float_as_uint(v.z) << 32) | (unsigned)(kb + 2); if (p < best) best = p;
        p = ((unsigned long long)__float_as_uint(v.w) << 32) | (unsigned)(kb + 3); if (p < best) best = p;
    }
    #pragma unroll
    for (int off = 16; off; off >>= 1) {
        unsigned long long o = __shfl_xor_sync(0xffffffffu, best, off);
        if (o < best) best = o;
    }
    const float minv = __uint_as_float((unsigned)(best >> 32));
    const float thr  = minv + DELTA;

    // Pass 2: exact recheck of near-tie candidates (ascending-c fp32 FMA
    // chain == bit-identical to the R2-passing kernel's accumulation).
    const float a = g_anorm[row];
    const float* xr = xrow[wid];
    unsigned long long ebest = 0xFFFFFFFFFFFFFFFFull;
    #pragma unroll
    for (int i = 0; i < 8; ++i) {
        #pragma unroll
        for (int j = 0; j < 4; ++j) {
            if (dv[i * 4 + j] <= thr) {
                int k = i * 128 + lane * 4 + j;
                const float* cr = cb + (size_t)k * C_;
                float m2 = 0.f;
                #pragma unroll 8
                for (int c = 0; c < C_; ++c) m2 += xr[c] * cr[c];
                float s = (a + g_enorm[k]) - 2.0f * m2;
                unsigned long long p =
                    ((unsigned long long)__float_as_uint(s) << 32) | (unsigned)k;
                if (p < ebest) ebest = p;
            }
        }
    }
    #pragma unroll
    for (int off = 16; off; off >>= 1) {
        unsigned long long o = __shfl_xor_sync(0xffffffffu, ebest, off);
        if (o < ebest) ebest = o;
    }
    if (lane == 0) g_idx[row] = (int)(unsigned)(ebest & 0xFFFFFFFFull);
}

// ---------------------------------------------------------------------------
// Gather + straight-through output + loss (proven R2/R3 epilogue)
// ---------------------------------------------------------------------------
__global__ __launch_bounds__(256)
void gather_kernel(const float* __restrict__ x,
                   const float* __restrict__ cb,
                   float* __restrict__ out)
{
    __shared__ int   srow[128];
    __shared__ float wsum[8];

    const int tid = threadIdx.x;
    const int blk = blockIdx.x;
    const int b   = blk >> 3;
    const int hw0 = (blk & 7) << 7;
    const int m0  = blk << 7;

    if (tid < 128) {
        int idx = g_idx[m0 + tid];
        srow[tid] = idx;
        out[QSIZE + 1 + m0 + tid] = (float)idx;
    }
    __syncthreads();

    const float* xblk = x   + (size_t)b * (C_ * HW_) + hw0;
    float*       qblk = out + (size_t)b * (C_ * HW_) + hw0;
    float lsum = 0.f;
    #pragma unroll 4
    for (int it = 0; it < 32; ++it) {
        int l  = it * 256 + tid;
        int m4 = (l & 31) << 2;
        int c  = l >> 5;
        float4 xv = *reinterpret_cast<const float4*>(xblk + c * HW_ + m4);
        float q0 = __ldg(cb + (size_t)srow[m4 + 0] * C_ + c);
        float q1 = __ldg(cb + (size_t)srow[m4 + 1] * C_ + c);
        float q2 = __ldg(cb + (size_t)srow[m4 + 2] * C_ + c);
        float q3 = __ldg(cb + (size_t)srow[m4 + 3] * C_ + c);
        float d0 = q0 - xv.x, d1 = q1 - xv.y, d2 = q2 - xv.z, d3 = q3 - xv.w;
        float4 o;
        o.x = xv.x + d0; o.y = xv.y + d1; o.z = xv.z + d2; o.w = xv.w + d3;
        *reinterpret_cast<float4*>(qblk + c * HW_ + m4) = o;
        lsum += d0 * d0 + d1 * d1 + d2 * d2 + d3 * d3;
    }

    #pragma unroll
    for (int off = 16; off; off >>= 1)
        lsum += __shfl_xor_sync(0xffffffffu, lsum, off);
    if ((tid & 31) == 0) wsum[tid >> 5] = lsum;
    __syncthreads();
    if (tid == 0) {
        float s = 0.f;
        #pragma unroll
        for (int w = 0; w < 8; ++w) s += wsum[w];
        atomicAdd(&g_loss, s);
    }
}

extern "C" void kernel_launch(void* const* d_in, const int* in_sizes, int n_in,
                              void* d_out, int out_size) {
    (void)in_sizes; (void)n_in; (void)out_size;
    const float* x  = (const float*)d_in[0];
    const float* cb = (const float*)d_in[1];
    float* out = (float*)d_out;

    static bool attr_done = false;
    if (!attr_done) {
        cudaFuncSetAttribute(vq_gemm_kernel,
                             cudaFuncAttributeMaxDynamicSharedMemorySize, SM_GEMM);
        attr_done = true;
    }

    zero_loss_kernel<<<1, 1>>>();
    enorm_kernel<<<4, 256>>>(cb);
    anorm_kernel<<<128, 256>>>(x);
    prep_cb_kernel<<<1024, 256>>>(cb);
    prep_x_kernel<<<2048, 256>>>(x);
    {
        dim3 grid(256, 4);
        vq_gemm_kernel<<<grid, 256, SM_GEMM>>>();
    }
    recheck_kernel<<<4096, 256>>>(cb);
    gather_kernel<<<256, 256>>>(x, cb, out);
    finalize_kernel<<<1, 1>>>(out);
}